// round 1
// baseline (speedup 1.0000x reference)
#include <cuda_runtime.h>
#include <cstdint>
#include <cstddef>

#define DD   1024
#define HH   4096
#define EE   8
#define NTOK 8192
#define CAP  8192

// ---- device scratch (static globals: no runtime allocation) ----
__device__ int   g_counts[EE];
__device__ int   g_padded[EE];
__device__ int   g_tokens[EE * CAP];
__device__ float g_wt[EE * CAP];
// h scratch: [expert][slot][H]  (only ~16k of 64k slots touched; bss, zero-init)
__device__ float g_h[268435456ULL];  // 8*8192*4096 floats = 1 GiB

// ---- helpers ----
__device__ __forceinline__ uint32_t f2tf(float x) {
    uint32_t r;
    asm("cvt.rna.tf32.f32 %0, %1;" : "=r"(r) : "f"(x));
    return r;
}

__device__ __forceinline__ void mma8(float c[4], const uint32_t a[4], const uint32_t b[2]) {
    asm volatile(
        "mma.sync.aligned.m16n8k8.row.col.f32.tf32.tf32.f32 "
        "{%0,%1,%2,%3}, {%4,%5,%6,%7}, {%8,%9}, {%0,%1,%2,%3};"
        : "+f"(c[0]), "+f"(c[1]), "+f"(c[2]), "+f"(c[3])
        : "r"(a[0]), "r"(a[1]), "r"(a[2]), "r"(a[3]),
          "r"(b[0]), "r"(b[1]));
}

// ---- kernel 0: zero output + counters ----
__global__ void k_zero(float* __restrict__ out) {
    size_t n4 = (size_t)NTOK * DD / 4;
    float4 z = make_float4(0.f, 0.f, 0.f, 0.f);
    for (size_t j = (size_t)blockIdx.x * blockDim.x + threadIdx.x; j < n4;
         j += (size_t)gridDim.x * blockDim.x)
        reinterpret_cast<float4*>(out)[j] = z;
    if (blockIdx.x == 0 && threadIdx.x < EE) g_counts[threadIdx.x] = 0;
}

// ---- kernel 1: router (1 warp per token, fp32 exact-ish selection) ----
__global__ void k_router(const float* __restrict__ xs, const float* __restrict__ gw) {
    int warp = (int)((blockIdx.x * blockDim.x + threadIdx.x) >> 5);
    int lane = threadIdx.x & 31;
    if (warp >= NTOK) return;

    const float* x = xs + (size_t)warp * DD;
    float xr[32];
#pragma unroll
    for (int i = 0; i < 32; i++) xr[i] = x[lane + 32 * i];

    float logit[EE];
#pragma unroll
    for (int e = 0; e < EE; e++) {
        const float* g = gw + e * DD;
        float a = 0.f;
#pragma unroll
        for (int i = 0; i < 32; i++) a += xr[i] * g[lane + 32 * i];
#pragma unroll
        for (int o = 16; o; o >>= 1) a += __shfl_xor_sync(0xFFFFFFFFu, a, o);
        logit[e] = a;
    }

    if (lane == 0) {
        float v0 = -1e30f, v1 = -1e30f;
        int i0 = 0, i1 = 0;
#pragma unroll
        for (int e = 0; e < EE; e++) {
            float v = logit[e];
            if (v > v0) { v1 = v0; i1 = i0; v0 = v; i0 = e; }
            else if (v > v1) { v1 = v; i1 = e; }
        }
        float e1 = __expf(v1 - v0);
        float s = 1.f + e1;
        float w0 = 1.f / s;
        float w1 = e1 / s;

        int s0 = atomicAdd(&g_counts[i0], 1);
        if (s0 < CAP) { g_tokens[i0 * CAP + s0] = warp; g_wt[i0 * CAP + s0] = w0; }
        int s1 = atomicAdd(&g_counts[i1], 1);
        if (s1 < CAP) { g_tokens[i1 * CAP + s1] = warp; g_wt[i1 * CAP + s1] = w1; }
    }
}

// ---- kernel 2: pad each expert list to multiple of 128 with weight-0 dummies ----
__global__ void k_pad() {
    int e = threadIdx.x >> 5;
    int lane = threadIdx.x & 31;
    if (e < EE) {
        int c = g_counts[e];
        if (c > CAP) c = CAP;
        int p = (c + 127) & ~127;
        if (p > CAP) p = CAP;
        for (int s = c + lane; s < p; s += 32) {
            g_tokens[e * CAP + s] = 0;
            g_wt[e * CAP + s] = 0.f;
        }
        if (lane == 0) g_padded[e] = p;
    }
}

// ---- GEMM1: h = relu(X_gathered @ W1[e]),  M=tokens, N=H, K=D ----
__global__ __launch_bounds__(256) void k_gemm1(const float* __restrict__ xs,
                                               const float* __restrict__ w1) {
    const int e = blockIdx.z;
    const int Mp = g_padded[e];
    const int m0 = blockIdx.y * 128;
    if (m0 >= Mp) return;
    const int n0 = blockIdx.x * 128;

    __shared__ uint32_t As[128 * 36];   // row-major [m][k], stride 36 -> conflict-free frags
    __shared__ uint32_t Bs[32 * 136];   // [k][n], stride 136 -> conflict-free frags
    __shared__ int toks[128];

    const int tid = threadIdx.x;
    if (tid < 128) toks[tid] = g_tokens[e * CAP + m0 + tid];
    __syncthreads();

    const int lane = tid & 31;
    const int wid = tid >> 5;
    const int wm = wid & 3;   // 4 warps along M (32 rows each)
    const int wn = wid >> 2;  // 2 warps along N (64 cols each)
    const int g = lane >> 2;
    const int tg = lane & 3;

    float acc[2][8][4];
#pragma unroll
    for (int i = 0; i < 2; i++)
#pragma unroll
        for (int j = 0; j < 8; j++)
#pragma unroll
            for (int k = 0; k < 4; k++) acc[i][j][k] = 0.f;

    const float* Bg = w1 + (size_t)e * DD * HH + n0;

    for (int k0 = 0; k0 < DD; k0 += 32) {
        // stage A (gathered token rows), convert to tf32
#pragma unroll
        for (int i = 0; i < 4; i++) {
            int j = tid + 256 * i;          // float4 index 0..1023
            int row = j >> 3, kq = j & 7;
            float4 v = *reinterpret_cast<const float4*>(
                xs + (size_t)toks[row] * DD + k0 + kq * 4);
            uint32_t* d = &As[row * 36 + kq * 4];
            d[0] = f2tf(v.x); d[1] = f2tf(v.y); d[2] = f2tf(v.z); d[3] = f2tf(v.w);
        }
        // stage B (w1 rows)
#pragma unroll
        for (int i = 0; i < 4; i++) {
            int j = tid + 256 * i;
            int k = j >> 5, nq = j & 31;
            float4 v = *reinterpret_cast<const float4*>(
                Bg + (size_t)(k0 + k) * HH + nq * 4);
            uint32_t* d = &Bs[k * 136 + nq * 4];
            d[0] = f2tf(v.x); d[1] = f2tf(v.y); d[2] = f2tf(v.z); d[3] = f2tf(v.w);
        }
        __syncthreads();

#pragma unroll
        for (int ks = 0; ks < 4; ks++) {
            const int kk = ks * 8;
            uint32_t a[2][4];
#pragma unroll
            for (int ma = 0; ma < 2; ma++) {
                int r = wm * 32 + ma * 16 + g;
                a[ma][0] = As[r * 36 + kk + tg];
                a[ma][1] = As[(r + 8) * 36 + kk + tg];
                a[ma][2] = As[r * 36 + kk + tg + 4];
                a[ma][3] = As[(r + 8) * 36 + kk + tg + 4];
            }
#pragma unroll
            for (int na = 0; na < 8; na++) {
                uint32_t b[2];
                int c = wn * 64 + na * 8 + g;
                b[0] = Bs[(kk + tg) * 136 + c];
                b[1] = Bs[(kk + tg + 4) * 136 + c];
                mma8(acc[0][na], a[0], b);
                mma8(acc[1][na], a[1], b);
            }
        }
        __syncthreads();
    }

    // epilogue: relu -> g_h
#pragma unroll
    for (int ma = 0; ma < 2; ma++) {
        int r = wm * 32 + ma * 16 + g;
#pragma unroll
        for (int na = 0; na < 8; na++) {
            int c = n0 + wn * 64 + na * 8 + 2 * tg;
            float* p0 = g_h + (size_t)(e * CAP + m0 + r) * HH + c;
            float* p1 = g_h + (size_t)(e * CAP + m0 + r + 8) * HH + c;
            float2 v0 = make_float2(fmaxf(acc[ma][na][0], 0.f), fmaxf(acc[ma][na][1], 0.f));
            float2 v1 = make_float2(fmaxf(acc[ma][na][2], 0.f), fmaxf(acc[ma][na][3], 0.f));
            *reinterpret_cast<float2*>(p0) = v0;
            *reinterpret_cast<float2*>(p1) = v1;
        }
    }
}

// ---- GEMM2: out += wt * (h @ W2[e]),  M=tokens, N=D, K=H ----
__global__ __launch_bounds__(256) void k_gemm2(const float* __restrict__ w2,
                                               float* __restrict__ out) {
    const int e = blockIdx.z;
    const int Mp = g_padded[e];
    const int m0 = blockIdx.y * 128;
    if (m0 >= Mp) return;
    const int n0 = blockIdx.x * 128;

    __shared__ uint32_t As[128 * 36];
    __shared__ uint32_t Bs[32 * 136];
    __shared__ int toks[128];
    __shared__ float wts[128];

    const int tid = threadIdx.x;
    if (tid < 128) {
        toks[tid] = g_tokens[e * CAP + m0 + tid];
        wts[tid] = g_wt[e * CAP + m0 + tid];
    }
    __syncthreads();

    const int lane = tid & 31;
    const int wid = tid >> 5;
    const int wm = wid & 3;
    const int wn = wid >> 2;
    const int g = lane >> 2;
    const int tg = lane & 3;

    float acc[2][8][4];
#pragma unroll
    for (int i = 0; i < 2; i++)
#pragma unroll
        for (int j = 0; j < 8; j++)
#pragma unroll
            for (int k = 0; k < 4; k++) acc[i][j][k] = 0.f;

    const float* Ag = g_h + (size_t)(e * CAP + m0) * HH;
    const float* Bg = w2 + (size_t)e * HH * DD + n0;

    for (int k0 = 0; k0 < HH; k0 += 32) {
#pragma unroll
        for (int i = 0; i < 4; i++) {
            int j = tid + 256 * i;
            int row = j >> 3, kq = j & 7;
            float4 v = *reinterpret_cast<const float4*>(
                Ag + (size_t)row * HH + k0 + kq * 4);
            uint32_t* d = &As[row * 36 + kq * 4];
            d[0] = f2tf(v.x); d[1] = f2tf(v.y); d[2] = f2tf(v.z); d[3] = f2tf(v.w);
        }
#pragma unroll
        for (int i = 0; i < 4; i++) {
            int j = tid + 256 * i;
            int k = j >> 5, nq = j & 31;
            float4 v = *reinterpret_cast<const float4*>(
                Bg + (size_t)(k0 + k) * DD + nq * 4);
            uint32_t* d = &Bs[k * 136 + nq * 4];
            d[0] = f2tf(v.x); d[1] = f2tf(v.y); d[2] = f2tf(v.z); d[3] = f2tf(v.w);
        }
        __syncthreads();

#pragma unroll
        for (int ks = 0; ks < 4; ks++) {
            const int kk = ks * 8;
            uint32_t a[2][4];
#pragma unroll
            for (int ma = 0; ma < 2; ma++) {
                int r = wm * 32 + ma * 16 + g;
                a[ma][0] = As[r * 36 + kk + tg];
                a[ma][1] = As[(r + 8) * 36 + kk + tg];
                a[ma][2] = As[r * 36 + kk + tg + 4];
                a[ma][3] = As[(r + 8) * 36 + kk + tg + 4];
            }
#pragma unroll
            for (int na = 0; na < 8; na++) {
                uint32_t b[2];
                int c = wn * 64 + na * 8 + g;
                b[0] = Bs[(kk + tg) * 136 + c];
                b[1] = Bs[(kk + tg + 4) * 136 + c];
                mma8(acc[0][na], a[0], b);
                mma8(acc[1][na], a[1], b);
            }
        }
        __syncthreads();
    }

    // epilogue: weighted scatter-add into out (2 adds per element total -> deterministic)
#pragma unroll
    for (int ma = 0; ma < 2; ma++) {
        int r = wm * 32 + ma * 16 + g;
        int t0 = toks[r];
        float w0 = wts[r];
        int t1 = toks[r + 8];
        float w1v = wts[r + 8];
#pragma unroll
        for (int na = 0; na < 8; na++) {
            int c = n0 + wn * 64 + na * 8 + 2 * tg;
            atomicAdd(&out[(size_t)t0 * DD + c], w0 * acc[ma][na][0]);
            atomicAdd(&out[(size_t)t0 * DD + c + 1], w0 * acc[ma][na][1]);
            atomicAdd(&out[(size_t)t1 * DD + c], w1v * acc[ma][na][2]);
            atomicAdd(&out[(size_t)t1 * DD + c + 1], w1v * acc[ma][na][3]);
        }
    }
}

extern "C" void kernel_launch(void* const* d_in, const int* in_sizes, int n_in,
                              void* d_out, int out_size) {
    const float* xs = (const float*)d_in[0];
    const float* gw = (const float*)d_in[1];
    const float* w1 = (const float*)d_in[2];
    const float* w2 = (const float*)d_in[3];
    float* out = (float*)d_out;

    k_zero<<<2048, 256>>>(out);
    k_router<<<NTOK / 8, 256>>>(xs, gw);
    k_pad<<<1, 256>>>();

    dim3 grid1(HH / 128, NTOK / 128, EE);
    k_gemm1<<<grid1, 256>>>(xs, w1);

    dim3 grid2(DD / 128, NTOK / 128, EE);
    k_gemm2<<<grid2, 256>>>(w2, out);
}

// round 3
// speedup vs baseline: 3.2659x; 3.2659x over previous
#include <cuda_runtime.h>
#include <cuda_fp16.h>
#include <cstdint>
#include <cstddef>

#define DD   1024
#define HH   4096
#define EE   8
#define NTOK 8192
#define CAP  8192
#define NSTAGE 3
#define STAGE_BYTES 32768            // 16KB A + 16KB B per stage
#define SMEM_TOKS (NSTAGE * STAGE_BYTES)
#define SMEM_WTS  (SMEM_TOKS + 512)
#define SMEM_SZ   (SMEM_WTS + 512)   // 99328 bytes

// ---- device scratch (static: no runtime allocation) ----
__device__ int    g_counts[EE];
__device__ int    g_padded[EE];
__device__ int    g_tokens[EE * CAP];
__device__ float  g_wt[EE * CAP];
__device__ __half g_xh[(size_t)NTOK * DD];          // x in fp16, 16MB
__device__ __half g_w1t[(size_t)EE * HH * DD];      // [e][h][d] fp16, 64MB
__device__ __half g_w2t[(size_t)EE * DD * HH];      // [e][d][h] fp16, 64MB
__device__ __half g_h[(size_t)EE * CAP * HH];       // relu(h) fp16, 128MB (sparse use)

// ---- helpers ----
__device__ __forceinline__ uint32_t smem_u32(const void* p) {
    uint32_t a;
    asm("{ .reg .u64 t; cvta.to.shared.u64 t, %1; cvt.u32.u64 %0, t; }" : "=r"(a) : "l"(p));
    return a;
}
__device__ __forceinline__ void cp_async16(uint32_t dst, const void* src) {
    asm volatile("cp.async.cg.shared.global [%0], [%1], 16;" :: "r"(dst), "l"(src) : "memory");
}
__device__ __forceinline__ void cp_commit() {
    asm volatile("cp.async.commit_group;" ::: "memory");
}
__device__ __forceinline__ void cp_wait1() {
    asm volatile("cp.async.wait_group 1;" ::: "memory");
}
__device__ __forceinline__ void ldsm4(uint32_t r[4], uint32_t addr) {
    asm volatile("ldmatrix.sync.aligned.m8n8.x4.shared.b16 {%0,%1,%2,%3}, [%4];"
                 : "=r"(r[0]), "=r"(r[1]), "=r"(r[2]), "=r"(r[3]) : "r"(addr));
}
__device__ __forceinline__ void mma16816(float c[4], const uint32_t a[4], uint32_t b0, uint32_t b1) {
    asm volatile(
        "mma.sync.aligned.m16n8k16.row.col.f32.f16.f16.f32 "
        "{%0,%1,%2,%3},{%4,%5,%6,%7},{%8,%9},{%0,%1,%2,%3};"
        : "+f"(c[0]), "+f"(c[1]), "+f"(c[2]), "+f"(c[3])
        : "r"(a[0]), "r"(a[1]), "r"(a[2]), "r"(a[3]), "r"(b0), "r"(b1));
}

// ---- zero output + counters ----
__global__ void k_zero(float* __restrict__ out) {
    size_t n4 = (size_t)NTOK * DD / 4;
    float4 z = make_float4(0.f, 0.f, 0.f, 0.f);
    for (size_t j = (size_t)blockIdx.x * blockDim.x + threadIdx.x; j < n4;
         j += (size_t)gridDim.x * blockDim.x)
        reinterpret_cast<float4*>(out)[j] = z;
    if (blockIdx.x == 0 && threadIdx.x < EE) g_counts[threadIdx.x] = 0;
}

// ---- x fp32 -> fp16 ----
__global__ void k_cvt_x(const float* __restrict__ xs) {
    size_t i = (size_t)blockIdx.x * blockDim.x + threadIdx.x;  // float4 index
    float4 v = reinterpret_cast<const float4*>(xs)[i];
    __half2* o = reinterpret_cast<__half2*>(g_xh);
    o[2 * i]     = __floats2half2_rn(v.x, v.y);
    o[2 * i + 1] = __floats2half2_rn(v.z, v.w);
}

// ---- transpose + fp16-convert weights: dst[c][r] = h(src[r][c]) per expert ----
__global__ void k_tr(const float* __restrict__ src, __half* __restrict__ dst, int R, int C) {
    __shared__ float tile[32][33];
    const size_t eoff = (size_t)blockIdx.z * R * C;
    const int c0 = blockIdx.x * 32, r0 = blockIdx.y * 32;
    const int tx = threadIdx.x, ty = threadIdx.y;
#pragma unroll
    for (int i = 0; i < 4; i++)
        tile[ty + 8 * i][tx] = src[eoff + (size_t)(r0 + ty + 8 * i) * C + c0 + tx];
    __syncthreads();
#pragma unroll
    for (int i = 0; i < 4; i++)
        dst[eoff + (size_t)(c0 + ty + 8 * i) * R + r0 + tx] = __float2half_rn(tile[tx][ty + 8 * i]);
}

// ---- router (1 warp per token, fp32 selection) ----
__global__ void k_router(const float* __restrict__ xs, const float* __restrict__ gw) {
    int warp = (int)((blockIdx.x * blockDim.x + threadIdx.x) >> 5);
    int lane = threadIdx.x & 31;
    if (warp >= NTOK) return;

    const float* x = xs + (size_t)warp * DD;
    float xr[32];
#pragma unroll
    for (int i = 0; i < 32; i++) xr[i] = x[lane + 32 * i];

    float logit[EE];
#pragma unroll
    for (int e = 0; e < EE; e++) {
        const float* g = gw + e * DD;
        float a = 0.f;
#pragma unroll
        for (int i = 0; i < 32; i++) a += xr[i] * g[lane + 32 * i];
#pragma unroll
        for (int o = 16; o; o >>= 1) a += __shfl_xor_sync(0xFFFFFFFFu, a, o);
        logit[e] = a;
    }

    if (lane == 0) {
        float v0 = -1e30f, v1 = -1e30f;
        int i0 = 0, i1 = 0;
#pragma unroll
        for (int e = 0; e < EE; e++) {
            float v = logit[e];
            if (v > v0) { v1 = v0; i1 = i0; v0 = v; i0 = e; }
            else if (v > v1) { v1 = v; i1 = e; }
        }
        float e1 = __expf(v1 - v0);
        float s = 1.f + e1;
        float w0 = 1.f / s;
        float w1 = e1 / s;

        int s0 = atomicAdd(&g_counts[i0], 1);
        g_tokens[i0 * CAP + s0] = warp;
        g_wt[i0 * CAP + s0] = w0;
        int s1 = atomicAdd(&g_counts[i1], 1);
        g_tokens[i1 * CAP + s1] = warp;
        g_wt[i1 * CAP + s1] = w1;
    }
}

// ---- pad each expert list to multiple of 128 with weight-0 dummies ----
__global__ void k_pad() {
    int e = threadIdx.x >> 5;
    int lane = threadIdx.x & 31;
    if (e < EE) {
        int c = g_counts[e];
        if (c > CAP) c = CAP;
        int p = (c + 127) & ~127;
        if (p > CAP) p = CAP;
        for (int s = c + lane; s < p; s += 32) {
            g_tokens[e * CAP + s] = 0;
            g_wt[e * CAP + s] = 0.f;
        }
        if (lane == 0) g_padded[e] = p;
    }
}

// ---- fp16 tensor-core grouped GEMM, 128x128 CTA tile, BK=64, 3-stage cp.async ----
// IS1:  h[e,slot][n] = relu(sum_k x[tok][k] * w1t[e][n][k]),  K=DD
// !IS1: out[tok][n] += wt * sum_k h[e,slot][k] * w2t[e][n][k], K=HH
template <bool IS1>
__global__ __launch_bounds__(256, 2) void k_gemm(float* __restrict__ out) {
    const int e = blockIdx.z;
    const int m0 = blockIdx.y * 128;
    if (m0 >= g_padded[e]) return;
    const int n0 = blockIdx.x * 128;
    const int KDIM = IS1 ? DD : HH;
    const int T = KDIM / 64;

    extern __shared__ char smem[];
    const uint32_t sb = smem_u32(smem);
    int* toks = (int*)(smem + SMEM_TOKS);
    float* wts = (float*)(smem + SMEM_WTS);
    const int tid = threadIdx.x;

    if (tid < 128) {
        toks[tid] = g_tokens[e * CAP + m0 + tid];
        if (!IS1) wts[tid] = g_wt[e * CAP + m0 + tid];
    }
    __syncthreads();

    const __half* bsrc = IS1 ? g_w1t + ((size_t)e * HH + n0) * DD
                             : g_w2t + ((size_t)e * DD + n0) * HH;
    const __half* asrc0 = g_h + (size_t)(e * CAP + m0) * HH;  // !IS1 A base

    // stage loader: 128 rows x 64 halfs (128B) each for A and B, swizzled
    auto issue = [&](int kt) {
        const int s = kt % NSTAGE;
        const int k0 = kt * 64;
        const uint32_t Ab = sb + s * STAGE_BYTES;
        const uint32_t Bb = Ab + 16384;
#pragma unroll
        for (int i = 0; i < 4; i++) {
            int idx = tid + 256 * i;
            int row = idx >> 3, ch = idx & 7;
            const __half* sa = IS1 ? g_xh + (size_t)toks[row] * DD + k0 + ch * 8
                                   : asrc0 + (size_t)row * HH + k0 + ch * 8;
            cp_async16(Ab + row * 128 + ((ch ^ (row & 7)) << 4), sa);
        }
#pragma unroll
        for (int i = 0; i < 4; i++) {
            int idx = tid + 256 * i;
            int row = idx >> 3, ch = idx & 7;
            cp_async16(Bb + row * 128 + ((ch ^ (row & 7)) << 4),
                       bsrc + (size_t)row * KDIM + k0 + ch * 8);
        }
    };

    issue(0); cp_commit();
    issue(1); cp_commit();

    const int lane = tid & 31, wid = tid >> 5;
    const int wm = wid & 1, wn = wid >> 1;   // 2x4 warps over 128x128 (64x32 per warp)
    const int lrow = lane & 15, lk = lane >> 4, rsw = lane & 7;

    float acc[4][4][4];
#pragma unroll
    for (int a = 0; a < 4; a++)
#pragma unroll
        for (int b = 0; b < 4; b++)
#pragma unroll
            for (int c = 0; c < 4; c++) acc[a][b][c] = 0.f;

    for (int kt = 0; kt < T; kt++) {
        cp_wait1();
        __syncthreads();
        if (kt + 2 < T) issue(kt + 2);
        cp_commit();

        const uint32_t Ab = sb + (kt % NSTAGE) * STAGE_BYTES;
        const uint32_t Bb = Ab + 16384;
#pragma unroll
        for (int ks = 0; ks < 4; ks++) {
            uint32_t a[4][4], b[2][4];
            const uint32_t coff = (((ks << 1) | lk) ^ rsw) << 4;
#pragma unroll
            for (int mt = 0; mt < 4; mt++) {
                int row = wm * 64 + mt * 16 + lrow;
                ldsm4(a[mt], Ab + row * 128 + (((ks << 1) | lk) ^ rsw) * 16);
            }
#pragma unroll
            for (int nt2 = 0; nt2 < 2; nt2++) {
                int row = wn * 32 + nt2 * 16 + lrow;
                ldsm4(b[nt2], Bb + row * 128 + coff);
            }
#pragma unroll
            for (int mt = 0; mt < 4; mt++)
#pragma unroll
                for (int nt = 0; nt < 4; nt++) {
                    const int nt2 = nt >> 1, hi = nt & 1;
                    mma16816(acc[mt][nt], a[mt], b[nt2][hi], b[nt2][hi + 2]);
                }
        }
    }

    // epilogue
    const int g = lane >> 2, tg = lane & 3;
    if (IS1) {
#pragma unroll
        for (int mt = 0; mt < 4; mt++) {
            const size_t r0 = (size_t)(e * CAP + m0 + wm * 64 + mt * 16 + g);
            __half* p0 = g_h + r0 * HH + n0;
            __half* p1 = p0 + (size_t)8 * HH;
#pragma unroll
            for (int nt = 0; nt < 4; nt++) {
                const int c = wn * 32 + nt * 8 + tg * 2;
                const float* A = acc[mt][nt];
                *(__half2*)(p0 + c) = __floats2half2_rn(fmaxf(A[0], 0.f), fmaxf(A[1], 0.f));
                *(__half2*)(p1 + c) = __floats2half2_rn(fmaxf(A[2], 0.f), fmaxf(A[3], 0.f));
            }
        }
    } else {
#pragma unroll
        for (int mt = 0; mt < 4; mt++) {
            const int rl = wm * 64 + mt * 16 + g;
            const int t0 = toks[rl];
            const float w0 = wts[rl];
            const int t1 = toks[rl + 8];
            const float w1v = wts[rl + 8];
            float* o0 = out + (size_t)t0 * DD + n0;
            float* o1 = out + (size_t)t1 * DD + n0;
#pragma unroll
            for (int nt = 0; nt < 4; nt++) {
                const int c = wn * 32 + nt * 8 + tg * 2;
                const float* A = acc[mt][nt];
                atomicAdd(o0 + c,     w0 * A[0]);
                atomicAdd(o0 + c + 1, w0 * A[1]);
                atomicAdd(o1 + c,     w1v * A[2]);
                atomicAdd(o1 + c + 1, w1v * A[3]);
            }
        }
    }
}

extern "C" void kernel_launch(void* const* d_in, const int* in_sizes, int n_in,
                              void* d_out, int out_size) {
    const float* xs = (const float*)d_in[0];
    const float* gw = (const float*)d_in[1];
    const float* w1 = (const float*)d_in[2];
    const float* w2 = (const float*)d_in[3];
    float* out = (float*)d_out;

    static int attr_done = 0;
    cudaFuncSetAttribute(k_gemm<true>, cudaFuncAttributeMaxDynamicSharedMemorySize, SMEM_SZ);
    cudaFuncSetAttribute(k_gemm<false>, cudaFuncAttributeMaxDynamicSharedMemorySize, SMEM_SZ);
    (void)attr_done;

    __half* w1t; cudaGetSymbolAddress((void**)&w1t, g_w1t);
    __half* w2t; cudaGetSymbolAddress((void**)&w2t, g_w2t);

    k_zero<<<2048, 256>>>(out);
    k_cvt_x<<<(NTOK * DD / 4) / 256, 256>>>(xs);
    // w1 [E,D,H] -> w1t [E,H,D];  w2 [E,H,D] -> w2t [E,D,H]
    k_tr<<<dim3(HH / 32, DD / 32, EE), dim3(32, 8)>>>(w1, w1t, DD, HH);
    k_tr<<<dim3(DD / 32, HH / 32, EE), dim3(32, 8)>>>(w2, w2t, HH, DD);
    k_router<<<NTOK / 8, 256>>>(xs, gw);
    k_pad<<<1, 256>>>();

    k_gemm<true><<<dim3(HH / 128, CAP / 128, EE), 256, SMEM_SZ>>>(out);
    k_gemm<false><<<dim3(DD / 128, CAP / 128, EE), 256, SMEM_SZ>>>(out);
}

// round 4
// speedup vs baseline: 3.6955x; 1.1316x over previous
#include <cuda_runtime.h>
#include <cuda_fp16.h>
#include <cstdint>
#include <cstddef>

#define DD   1024
#define HH   4096
#define EE   8
#define NTOK 8192
#define CAP  8192
#define NSTAGE 3
#define STAGE_BYTES 32768            // 16KB A (128m x 64k) + 16KB B (64k x 128n)
#define SMEM_TOKS (NSTAGE * STAGE_BYTES)
#define SMEM_WTS  (SMEM_TOKS + 512)
#define SMEM_SZ   (SMEM_WTS + 512)   // 99328 bytes

// ---- device scratch (static: no runtime allocation) ----
__device__ int    g_counts[EE];
__device__ int    g_padded[EE];
__device__ int    g_tokens[EE * CAP];
__device__ float  g_wt[EE * CAP];
__device__ __half g_xh[(size_t)NTOK * DD];          // x fp16, 16MB
__device__ __half g_w1h[(size_t)EE * DD * HH];      // w1 fp16 natural [e][d][h], 64MB
__device__ __half g_w2h[(size_t)EE * HH * DD];      // w2 fp16 natural [e][h][d], 64MB
__device__ __half g_h[(size_t)EE * CAP * HH];       // relu(h) fp16, 128MB (sparse use)

// ---- helpers ----
__device__ __forceinline__ uint32_t smem_u32(const void* p) {
    uint32_t a;
    asm("{ .reg .u64 t; cvta.to.shared.u64 t, %1; cvt.u32.u64 %0, t; }" : "=r"(a) : "l"(p));
    return a;
}
__device__ __forceinline__ void cp_async16(uint32_t dst, const void* src) {
    asm volatile("cp.async.cg.shared.global [%0], [%1], 16;" :: "r"(dst), "l"(src) : "memory");
}
__device__ __forceinline__ void cp_commit() {
    asm volatile("cp.async.commit_group;" ::: "memory");
}
__device__ __forceinline__ void cp_wait1() {
    asm volatile("cp.async.wait_group 1;" ::: "memory");
}
__device__ __forceinline__ void ldsm4(uint32_t r[4], uint32_t addr) {
    asm volatile("ldmatrix.sync.aligned.m8n8.x4.shared.b16 {%0,%1,%2,%3}, [%4];"
                 : "=r"(r[0]), "=r"(r[1]), "=r"(r[2]), "=r"(r[3]) : "r"(addr));
}
__device__ __forceinline__ void ldsm4t(uint32_t r[4], uint32_t addr) {
    asm volatile("ldmatrix.sync.aligned.m8n8.x4.trans.shared.b16 {%0,%1,%2,%3}, [%4];"
                 : "=r"(r[0]), "=r"(r[1]), "=r"(r[2]), "=r"(r[3]) : "r"(addr));
}
__device__ __forceinline__ void mma16816(float c[4], const uint32_t a[4], uint32_t b0, uint32_t b1) {
    asm volatile(
        "mma.sync.aligned.m16n8k16.row.col.f32.f16.f16.f32 "
        "{%0,%1,%2,%3},{%4,%5,%6,%7},{%8,%9},{%0,%1,%2,%3};"
        : "+f"(c[0]), "+f"(c[1]), "+f"(c[2]), "+f"(c[3])
        : "r"(a[0]), "r"(a[1]), "r"(a[2]), "r"(a[3]), "r"(b0), "r"(b1));
}

// ---- zero output + counters ----
__global__ void k_zero(float* __restrict__ out) {
    size_t n4 = (size_t)NTOK * DD / 4;
    float4 z = make_float4(0.f, 0.f, 0.f, 0.f);
    for (size_t j = (size_t)blockIdx.x * blockDim.x + threadIdx.x; j < n4;
         j += (size_t)gridDim.x * blockDim.x)
        reinterpret_cast<float4*>(out)[j] = z;
    if (blockIdx.x == 0 && threadIdx.x < EE) g_counts[threadIdx.x] = 0;
}

// ---- streaming fp32 -> fp16 convert (8 elems / 16B-write per thread) ----
__global__ void k_cvt(const float* __restrict__ src, __half* __restrict__ dst) {
    size_t i = ((size_t)blockIdx.x * blockDim.x + threadIdx.x) * 8;
    float4 a = *reinterpret_cast<const float4*>(src + i);
    float4 b = *reinterpret_cast<const float4*>(src + i + 4);
    __half2 h[4];
    h[0] = __floats2half2_rn(a.x, a.y);
    h[1] = __floats2half2_rn(a.z, a.w);
    h[2] = __floats2half2_rn(b.x, b.y);
    h[3] = __floats2half2_rn(b.z, b.w);
    *reinterpret_cast<uint4*>(dst + i) = *reinterpret_cast<uint4*>(h);
}

// ---- router (1 warp per token, fp32 selection) ----
__global__ void k_router(const float* __restrict__ xs, const float* __restrict__ gw) {
    int warp = (int)((blockIdx.x * blockDim.x + threadIdx.x) >> 5);
    int lane = threadIdx.x & 31;
    if (warp >= NTOK) return;

    const float* x = xs + (size_t)warp * DD;
    float xr[32];
#pragma unroll
    for (int i = 0; i < 32; i++) xr[i] = x[lane + 32 * i];

    float logit[EE];
#pragma unroll
    for (int e = 0; e < EE; e++) {
        const float* g = gw + e * DD;
        float a = 0.f;
#pragma unroll
        for (int i = 0; i < 32; i++) a += xr[i] * g[lane + 32 * i];
#pragma unroll
        for (int o = 16; o; o >>= 1) a += __shfl_xor_sync(0xFFFFFFFFu, a, o);
        logit[e] = a;
    }

    if (lane == 0) {
        float v0 = -1e30f, v1 = -1e30f;
        int i0 = 0, i1 = 0;
#pragma unroll
        for (int e = 0; e < EE; e++) {
            float v = logit[e];
            if (v > v0) { v1 = v0; i1 = i0; v0 = v; i0 = e; }
            else if (v > v1) { v1 = v; i1 = e; }
        }
        float e1 = __expf(v1 - v0);
        float s = 1.f + e1;
        float w0 = 1.f / s;
        float w1 = e1 / s;

        int s0 = atomicAdd(&g_counts[i0], 1);
        g_tokens[i0 * CAP + s0] = warp;
        g_wt[i0 * CAP + s0] = w0;
        int s1 = atomicAdd(&g_counts[i1], 1);
        g_tokens[i1 * CAP + s1] = warp;
        g_wt[i1 * CAP + s1] = w1;
    }
}

// ---- pad each expert list to multiple of 128 with weight-0 dummies ----
__global__ void k_pad() {
    int e = threadIdx.x >> 5;
    int lane = threadIdx.x & 31;
    if (e < EE) {
        int c = g_counts[e];
        if (c > CAP) c = CAP;
        int p = (c + 127) & ~127;
        if (p > CAP) p = CAP;
        for (int s = c + lane; s < p; s += 32) {
            g_tokens[e * CAP + s] = 0;
            g_wt[e * CAP + s] = 0.f;
        }
        if (lane == 0) g_padded[e] = p;
    }
}

// ---- fp16 tensor-core grouped GEMM ----
// CTA tile 128x128, BK=64, 3-stage cp.async, 4 warps (2x2), warp tile 64x64.
// A: [m][k] smem, ldmatrix non-trans.  B: [k][n] smem (natural weight layout),
// ldmatrix.trans ({r0,r1}=n8-group0, {r2,r3}=n8-group1).
// IS1:  h[e,slot][n] = relu(sum_k x[tok][k] * w1[e][k][n]),   K=DD, Bstride=HH
// !IS1: out[tok][n] += wt * sum_k h[e,slot][k] * w2[e][k][n], K=HH, Bstride=DD
template <bool IS1>
__global__ __launch_bounds__(128, 2) void k_gemm(float* __restrict__ out) {
    const int e = blockIdx.z;
    const int m0 = blockIdx.y * 128;
    if (m0 >= g_padded[e]) return;
    const int n0 = blockIdx.x * 128;
    const int KDIM = IS1 ? DD : HH;
    const int BSTR = IS1 ? HH : DD;
    const int T = KDIM / 64;

    extern __shared__ char smem[];
    const uint32_t sb = smem_u32(smem);
    int* toks = (int*)(smem + SMEM_TOKS);
    float* wts = (float*)(smem + SMEM_WTS);
    const int tid = threadIdx.x;

    {
        toks[tid] = g_tokens[e * CAP + m0 + tid];
        if (!IS1) wts[tid] = g_wt[e * CAP + m0 + tid];
    }
    __syncthreads();

    const __half* bsrc = IS1 ? g_w1h + (size_t)e * DD * HH + n0
                             : g_w2h + (size_t)e * HH * DD + n0;
    const __half* asrc0 = g_h + (size_t)(e * CAP + m0) * HH;  // !IS1 A base

    auto issue = [&](int kt) {
        const int s = kt % NSTAGE;
        const int k0 = kt * 64;
        const uint32_t Ab = sb + s * STAGE_BYTES;
        const uint32_t Bb = Ab + 16384;
        // A: 128 rows x 8 chunks(16B)
#pragma unroll
        for (int i = 0; i < 8; i++) {
            int idx = tid + 128 * i;
            int row = idx >> 3, c = idx & 7;
            const __half* sa = IS1 ? g_xh + (size_t)toks[row] * DD + k0 + c * 8
                                   : asrc0 + (size_t)row * HH + k0 + c * 8;
            cp_async16(Ab + row * 128 + ((c ^ (row & 7)) << 4), sa);
        }
        // B: 64 k-rows x 16 chunks(16B) (n contiguous)
#pragma unroll
        for (int i = 0; i < 8; i++) {
            int idx = tid + 128 * i;
            int row = idx >> 4, c = idx & 15;
            cp_async16(Bb + row * 256 + ((c ^ (row & 7)) << 4),
                       bsrc + (size_t)(k0 + row) * BSTR + c * 8);
        }
    };

    issue(0); cp_commit();
    issue(1); cp_commit();

    const int lane = tid & 31, wid = tid >> 5;
    const int wm = wid & 1, wn = wid >> 1;  // 2x2 warps, 64x64 each
    const int lrow = lane & 15, lk = lane >> 4;

    float acc[4][8][4];
#pragma unroll
    for (int a = 0; a < 4; a++)
#pragma unroll
        for (int b = 0; b < 8; b++)
#pragma unroll
            for (int c = 0; c < 4; c++) acc[a][b][c] = 0.f;

    for (int kt = 0; kt < T; kt++) {
        cp_wait1();
        __syncthreads();
        if (kt + 2 < T) issue(kt + 2);
        cp_commit();

        const uint32_t Ab = sb + (kt % NSTAGE) * STAGE_BYTES;
        const uint32_t Bb = Ab + 16384;
#pragma unroll
        for (int ks = 0; ks < 4; ks++) {
            uint32_t a[4][4], b[4][4];
#pragma unroll
            for (int mt = 0; mt < 4; mt++) {
                int row = wm * 64 + mt * 16 + lrow;
                ldsm4(a[mt], Ab + row * 128 + ((((ks << 1) | lk) ^ (row & 7)) << 4));
            }
#pragma unroll
            for (int nt2 = 0; nt2 < 4; nt2++) {
                int krow = ks * 16 + lrow;
                int chunk = wn * 8 + nt2 * 2 + lk;
                ldsm4t(b[nt2], Bb + krow * 256 + ((chunk ^ (krow & 7)) << 4));
            }
#pragma unroll
            for (int mt = 0; mt < 4; mt++)
#pragma unroll
                for (int nt = 0; nt < 8; nt++) {
                    const int nt2 = nt >> 1, sub = nt & 1;
                    mma16816(acc[mt][nt], a[mt], b[nt2][2 * sub], b[nt2][2 * sub + 1]);
                }
        }
    }

    // epilogue
    const int g = lane >> 2, tg = lane & 3;
    if (IS1) {
#pragma unroll
        for (int mt = 0; mt < 4; mt++) {
            const size_t r0 = (size_t)(e * CAP + m0 + wm * 64 + mt * 16 + g);
            __half* p0 = g_h + r0 * HH + n0;
            __half* p1 = p0 + (size_t)8 * HH;
#pragma unroll
            for (int nt = 0; nt < 8; nt++) {
                const int c = wn * 64 + nt * 8 + tg * 2;
                const float* A = acc[mt][nt];
                *(__half2*)(p0 + c) = __floats2half2_rn(fmaxf(A[0], 0.f), fmaxf(A[1], 0.f));
                *(__half2*)(p1 + c) = __floats2half2_rn(fmaxf(A[2], 0.f), fmaxf(A[3], 0.f));
            }
        }
    } else {
#pragma unroll
        for (int mt = 0; mt < 4; mt++) {
            const int rl = wm * 64 + mt * 16 + g;
            const int t0 = toks[rl];
            const float w0 = wts[rl];
            const int t1 = toks[rl + 8];
            const float w1v = wts[rl + 8];
            float* o0 = out + (size_t)t0 * DD + n0;
            float* o1 = out + (size_t)t1 * DD + n0;
#pragma unroll
            for (int nt = 0; nt < 8; nt++) {
                const int c = wn * 64 + nt * 8 + tg * 2;
                const float* A = acc[mt][nt];
                atomicAdd(o0 + c,     w0 * A[0]);
                atomicAdd(o0 + c + 1, w0 * A[1]);
                atomicAdd(o1 + c,     w1v * A[2]);
                atomicAdd(o1 + c + 1, w1v * A[3]);
            }
        }
    }
}

extern "C" void kernel_launch(void* const* d_in, const int* in_sizes, int n_in,
                              void* d_out, int out_size) {
    const float* xs = (const float*)d_in[0];
    const float* gw = (const float*)d_in[1];
    const float* w1 = (const float*)d_in[2];
    const float* w2 = (const float*)d_in[3];
    float* out = (float*)d_out;

    cudaFuncSetAttribute(k_gemm<true>, cudaFuncAttributeMaxDynamicSharedMemorySize, SMEM_SZ);
    cudaFuncSetAttribute(k_gemm<false>, cudaFuncAttributeMaxDynamicSharedMemorySize, SMEM_SZ);

    __half* w1h; cudaGetSymbolAddress((void**)&w1h, g_w1h);
    __half* w2h; cudaGetSymbolAddress((void**)&w2h, g_w2h);
    __half* xh;  cudaGetSymbolAddress((void**)&xh,  g_xh);

    k_zero<<<2048, 256>>>(out);
    k_cvt<<<(NTOK * DD / 8) / 256, 256>>>(xs, xh);
    k_cvt<<<(EE * DD * HH / 8) / 256, 256>>>(w1, w1h);
    k_cvt<<<(EE * HH * DD / 8) / 256, 256>>>(w2, w2h);
    k_router<<<NTOK / 8, 256>>>(xs, gw);
    k_pad<<<1, 256>>>();

    k_gemm<true><<<dim3(HH / 128, CAP / 128, EE), 128, SMEM_SZ>>>(out);
    k_gemm<false><<<dim3(DD / 128, CAP / 128, EE), 128, SMEM_SZ>>>(out);
}